// round 5
// baseline (speedup 1.0000x reference)
#include <cuda_runtime.h>

#define T_LEN 1024
#define HID   64
#define SB    8          // batch streams per CTA (both directions in-CTA)
#define NTH   256        // threads: 0-127 forward group, 128-255 backward group

// Packed dual-fp32 FMA (Blackwell sm_100+): two f32 MACs per instruction.
__device__ __forceinline__ unsigned long long ffma2(unsigned long long a,
                                                    unsigned long long b,
                                                    unsigned long long c) {
    unsigned long long d;
    asm("fma.rn.f32x2 %0, %1, %2, %3;" : "=l"(d) : "l"(a), "l"(b), "l"(c));
    return d;
}
__device__ __forceinline__ float f2lo(unsigned long long v) {
    union { unsigned long long u; float2 f; } a; a.u = v; return a.f.x;
}
__device__ __forceinline__ float f2hi(unsigned long long v) {
    union { unsigned long long u; float2 f; } a; a.u = v; return a.f.y;
}

__device__ __forceinline__ float fast_sigmoid(float x) {
    return __fdividef(1.0f, 1.0f + __expf(-x));
}
__device__ __forceinline__ float fast_tanh(float x) {
    return fmaf(-2.0f, __fdividef(1.0f, __expf(2.0f * x) + 1.0f), 1.0f);
}

__device__ __forceinline__ void bar_grp(int id) {
    asm volatile("bar.sync %0, %1;" :: "r"(id), "r"(128) : "memory");
}

struct __align__(16) Sm {
    float pb[SB][T_LEN];        // backward fc partials, indexed by OUTPUT time (32 KB)
    float h[2][2][SB][HID];     // double-buffered hidden: [buf][dir][stream][k] (8 KB)
    float abuf[2][HID][9];      // sig(i)*tanh(g), padded stride 9 (bank-free)
};

__global__ __launch_bounds__(NTH, 1)
void bilstm_kernel(const float* __restrict__ x,
                   const float* __restrict__ Wih_f, const float* __restrict__ Whh_f,
                   const float* __restrict__ bih_f, const float* __restrict__ bhh_f,
                   const float* __restrict__ Wih_b, const float* __restrict__ Whh_b,
                   const float* __restrict__ bih_b, const float* __restrict__ bhh_b,
                   const float* __restrict__ fc_w, const float* __restrict__ fc_b,
                   float* __restrict__ out)
{
    __shared__ Sm sm;

    const int tid   = threadIdx.x;
    const int d     = tid >> 7;              // 0 fwd, 1 bwd
    const int local = tid & 127;
    const int k     = local & 63;
    // Role A = (i,g) rows, Role B = (f,o) rows. Flip mapping for bwd so each
    // SMSP (warp%4) hosts exactly one A-warp and one B-warp.
    const bool roleA = d == 0 ? (local < 64) : (local >= 64);
    const int b0 = blockIdx.x * SB;

    // zero both h buffers (2*2*8*64 = 2048 floats)
    for (int idx = tid; idx < 2 * 2 * SB * HID; idx += NTH)
        (&sm.h[0][0][0][0])[idx] = 0.0f;

    const float* Whh = d ? Whh_b : Whh_f;
    const float* Wih = d ? Wih_b : Wih_f;
    const float* bih = d ? bih_b : bih_f;
    const float* bhh = d ? bhh_b : bhh_f;

    const int rA = roleA ? k         : (64 + k);   // i or f row
    const int rB = roleA ? (128 + k) : (192 + k);  // g or o row

    unsigned long long wkA[32], wkB[32];
    {
        const unsigned long long* wa = (const unsigned long long*)(Whh + rA * HID);
        const unsigned long long* wb = (const unsigned long long*)(Whh + rB * HID);
        #pragma unroll
        for (int i = 0; i < 32; ++i) { wkA[i] = __ldg(wa + i); wkB[i] = __ldg(wb + i); }
    }
    const float wihA  = Wih[rA], wihB = Wih[rB];
    const float baseA = bih[rA] + bhh[rA];
    const float baseB = bih[rB] + bhh[rB];

    // fc mapping for role-A threads: octet fj of stream fss
    const int fss = k >> 3, fj = k & 7;
    float4 fw0 = {0,0,0,0}, fw1 = {0,0,0,0};
    if (roleA) {
        fw0 = *(const float4*)(fc_w + d * HID + fj * 8);
        fw1 = *(const float4*)(fc_w + d * HID + fj * 8 + 4);
    }

    float c[SB], fg[SB], og[SB];
    #pragma unroll
    for (int ss = 0; ss < SB; ++ss) { c[ss] = 0.0f; fg[ss] = 0.0f; og[ss] = 0.0f; }

    __syncthreads();

    const int barid = 1 + d;
    const float* xrow = x + (long)b0 * T_LEN;

    for (int t = 0; t < T_LEN; ++t) {
        const int xt = d ? (T_LEN - 1 - t) : t;
        const float* hb = &sm.h[(t + 1) & 1][d][0][0];   // h(t-1)

        // ---- fused matvec + gate-transcendentals, stream-outer so MUFU hides
        //      under the next stream's FFMA window ----
        #pragma unroll
        for (int ss = 0; ss < SB; ++ss) {
            unsigned long long aA = 0ULL, aB = 0ULL;
            const ulonglong2* hv2 = (const ulonglong2*)(hb + ss * HID);
            #pragma unroll
            for (int i2 = 0; i2 < 16; ++i2) {
                ulonglong2 hv = hv2[i2];            // broadcast LDS.128
                aA = ffma2(hv.x, wkA[2 * i2],     aA);
                aA = ffma2(hv.y, wkA[2 * i2 + 1], aA);
                aB = ffma2(hv.x, wkB[2 * i2],     aB);
                aB = ffma2(hv.y, wkB[2 * i2 + 1], aB);
            }
            const float xv = __ldg(xrow + ss * T_LEN + xt);   // warp-uniform broadcast LDG
            const float zA = f2lo(aA) + f2hi(aA) + fmaf(xv, wihA, baseA);
            const float zB = f2lo(aB) + f2hi(aB) + fmaf(xv, wihB, baseB);
            if (roleA) {
                sm.abuf[d][k][ss] = fast_sigmoid(zA) * fast_tanh(zB);
            } else {
                fg[ss] = fast_sigmoid(zA);
                og[ss] = fast_sigmoid(zB);
            }
        }
        bar_grp(barid);

        if (roleA) {
            // fc dot for state index t-1; the reference does NOT flip the
            // backward outputs: out position t' pairs hf(t') with hb(t').
            if (t > 0) {
                const float* hp = &sm.h[(t + 1) & 1][d][fss][fj * 8];
                float4 h0 = *(const float4*)hp;
                float4 h1 = *(const float4*)(hp + 4);
                float p = fw0.x * h0.x + fw0.y * h0.y + fw0.z * h0.z + fw0.w * h0.w
                        + fw1.x * h1.x + fw1.y * h1.y + fw1.z * h1.z + fw1.w * h1.w;
                p += __shfl_xor_sync(0xffffffffu, p, 1);
                p += __shfl_xor_sync(0xffffffffu, p, 2);
                p += __shfl_xor_sync(0xffffffffu, p, 4);
                if (fj == 0) {
                    if (d == 0) out[(b0 + fss) * T_LEN + (t - 1)] = p;  // fwd partial -> gmem
                    else        sm.pb[fss][t - 1] = p;                   // bwd partial, SAME position
                }
            }
        } else {
            // cell/hidden update; writes h(t) into buf[t&1]
            float* hw = &sm.h[t & 1][d][0][0];
            #pragma unroll
            for (int ss = 0; ss < SB; ++ss) {
                c[ss] = fmaf(fg[ss], c[ss], sm.abuf[d][k][ss]);
                hw[ss * HID + k] = og[ss] * fast_tanh(c[ss]);
            }
        }
        bar_grp(barid);
    }

    // final fc dot for state index T_LEN-1 (h in buf[(T_LEN-1)&1] = buf[1])
    if (roleA) {
        const float* hp = &sm.h[(T_LEN - 1) & 1][d][fss][fj * 8];
        float4 h0 = *(const float4*)hp;
        float4 h1 = *(const float4*)(hp + 4);
        float p = fw0.x * h0.x + fw0.y * h0.y + fw0.z * h0.z + fw0.w * h0.w
                + fw1.x * h1.x + fw1.y * h1.y + fw1.z * h1.z + fw1.w * h1.w;
        p += __shfl_xor_sync(0xffffffffu, p, 1);
        p += __shfl_xor_sync(0xffffffffu, p, 2);
        p += __shfl_xor_sync(0xffffffffu, p, 4);
        if (fj == 0) {
            if (d == 0) out[(b0 + fss) * T_LEN + (T_LEN - 1)] = p;
            else        sm.pb[fss][T_LEN - 1] = p;
        }
    }

    __syncthreads();   // fwd's gmem partials + bwd's smem partials all visible

    const float fcb = fc_b[0];
    for (int idx = tid; idx < SB * T_LEN; idx += NTH) {
        int ss = idx >> 10, tt = idx & (T_LEN - 1);
        float* po = out + (b0 + ss) * T_LEN + tt;
        *po = *po + sm.pb[ss][tt] + fcb;
    }
}

extern "C" void kernel_launch(void* const* d_in, const int* in_sizes, int n_in,
                              void* d_out, int out_size) {
    const float* x     = (const float*)d_in[0];
    const float* Wih_f = (const float*)d_in[1];
    const float* Whh_f = (const float*)d_in[2];
    const float* bih_f = (const float*)d_in[3];
    const float* bhh_f = (const float*)d_in[4];
    const float* Wih_b = (const float*)d_in[5];
    const float* Whh_b = (const float*)d_in[6];
    const float* bih_b = (const float*)d_in[7];
    const float* bhh_b = (const float*)d_in[8];
    const float* fc_w  = (const float*)d_in[9];
    const float* fc_b  = (const float*)d_in[10];
    float* out = (float*)d_out;

    const int B = in_sizes[0] / T_LEN;   // 1024
    const int grid = B / SB;             // 128 CTAs

    bilstm_kernel<<<grid, NTH>>>(x, Wih_f, Whh_f, bih_f, bhh_f,
                                 Wih_b, Whh_b, bih_b, bhh_b,
                                 fc_w, fc_b, out);
    (void)n_in; (void)out_size;
}

// round 6
// speedup vs baseline: 1.0061x; 1.0061x over previous
#include <cuda_runtime.h>

#define T_LEN 1024
#define HID   64
#define SB    8          // batch streams per CTA (both directions in-CTA)
#define NTH   256        // threads: 0-127 forward group, 128-255 backward group

// Packed dual-fp32 FMA (Blackwell sm_100+): two f32 MACs per instruction.
__device__ __forceinline__ unsigned long long ffma2(unsigned long long a,
                                                    unsigned long long b,
                                                    unsigned long long c) {
    unsigned long long d;
    asm("fma.rn.f32x2 %0, %1, %2, %3;" : "=l"(d) : "l"(a), "l"(b), "l"(c));
    return d;
}
__device__ __forceinline__ float f2lo(unsigned long long v) {
    union { unsigned long long u; float2 f; } a; a.u = v; return a.f.x;
}
__device__ __forceinline__ float f2hi(unsigned long long v) {
    union { unsigned long long u; float2 f; } a; a.u = v; return a.f.y;
}

__device__ __forceinline__ float fast_sigmoid(float x) {
    return __fdividef(1.0f, 1.0f + __expf(-x));
}
__device__ __forceinline__ float fast_tanh(float x) {
    return fmaf(-2.0f, __fdividef(1.0f, __expf(2.0f * x) + 1.0f), 1.0f);
}

__device__ __forceinline__ void bar_grp(int id) {
    asm volatile("bar.sync %0, %1;" :: "r"(id), "r"(128) : "memory");
}

struct __align__(16) Sm {
    float pb[SB][T_LEN];        // backward fc partials, indexed by OUTPUT time (32 KB)
    float h[2][2][SB][HID];     // double-buffered hidden: [buf][dir][stream][k] (8 KB)
    float abuf[2][HID][9];      // sig(i)*tanh(g), padded stride 9 (bank-free)
};

__global__ __launch_bounds__(NTH, 1)
void bilstm_kernel(const float* __restrict__ x,
                   const float* __restrict__ Wih_f, const float* __restrict__ Whh_f,
                   const float* __restrict__ bih_f, const float* __restrict__ bhh_f,
                   const float* __restrict__ Wih_b, const float* __restrict__ Whh_b,
                   const float* __restrict__ bih_b, const float* __restrict__ bhh_b,
                   const float* __restrict__ fc_w, const float* __restrict__ fc_b,
                   float* __restrict__ out)
{
    __shared__ Sm sm;

    const int tid   = threadIdx.x;
    const int d     = tid >> 7;              // 0 fwd, 1 bwd
    const int local = tid & 127;
    const int k     = local & 63;
    // Role A = (i,g) rows, Role B = (f,o) rows. Flip mapping for bwd so each
    // SMSP (warp%4) hosts exactly one A-warp and one B-warp.
    const bool roleA = d == 0 ? (local < 64) : (local >= 64);
    const int b0 = blockIdx.x * SB;

    // zero both h buffers (2*2*8*64 = 2048 floats)
    for (int idx = tid; idx < 2 * 2 * SB * HID; idx += NTH)
        (&sm.h[0][0][0][0])[idx] = 0.0f;

    const float* Whh = d ? Whh_b : Whh_f;
    const float* Wih = d ? Wih_b : Wih_f;
    const float* bih = d ? bih_b : bih_f;
    const float* bhh = d ? bhh_b : bhh_f;

    const int rA = roleA ? k         : (64 + k);   // i or f row
    const int rB = roleA ? (128 + k) : (192 + k);  // g or o row

    unsigned long long wkA[32], wkB[32];
    {
        const unsigned long long* wa = (const unsigned long long*)(Whh + rA * HID);
        const unsigned long long* wb = (const unsigned long long*)(Whh + rB * HID);
        #pragma unroll
        for (int i = 0; i < 32; ++i) { wkA[i] = __ldg(wa + i); wkB[i] = __ldg(wb + i); }
    }
    const float wihA  = Wih[rA], wihB = Wih[rB];
    const float baseA = bih[rA] + bhh[rA];
    const float baseB = bih[rB] + bhh[rB];

    // fc mapping for role-A threads: octet fj of stream fss
    const int fss = k >> 3, fj = k & 7;
    float4 fw0 = {0,0,0,0}, fw1 = {0,0,0,0};
    if (roleA) {
        fw0 = *(const float4*)(fc_w + d * HID + fj * 8);
        fw1 = *(const float4*)(fc_w + d * HID + fj * 8 + 4);
    }

    float c[SB], fg[SB], og[SB];
    #pragma unroll
    for (int ss = 0; ss < SB; ++ss) { c[ss] = 0.0f; fg[ss] = 0.0f; og[ss] = 0.0f; }

    __syncthreads();

    const int barid = 1 + d;
    const float* xrow = x + (long)b0 * T_LEN;

    for (int t = 0; t < T_LEN; ++t) {
        const int xt = d ? (T_LEN - 1 - t) : t;
        const float* hb = &sm.h[(t + 1) & 1][d][0][0];   // h(t-1)

        // ---- fused matvec + gate-transcendentals, stream-outer so MUFU hides
        //      under the next stream's FFMA window ----
        #pragma unroll
        for (int ss = 0; ss < SB; ++ss) {
            unsigned long long aA = 0ULL, aB = 0ULL;
            const ulonglong2* hv2 = (const ulonglong2*)(hb + ss * HID);
            #pragma unroll
            for (int i2 = 0; i2 < 16; ++i2) {
                ulonglong2 hv = hv2[i2];            // broadcast LDS.128
                aA = ffma2(hv.x, wkA[2 * i2],     aA);
                aA = ffma2(hv.y, wkA[2 * i2 + 1], aA);
                aB = ffma2(hv.x, wkB[2 * i2],     aB);
                aB = ffma2(hv.y, wkB[2 * i2 + 1], aB);
            }
            const float xv = __ldg(xrow + ss * T_LEN + xt);   // warp-uniform broadcast LDG
            const float zA = f2lo(aA) + f2hi(aA) + fmaf(xv, wihA, baseA);
            const float zB = f2lo(aB) + f2hi(aB) + fmaf(xv, wihB, baseB);
            if (roleA) {
                sm.abuf[d][k][ss] = fast_sigmoid(zA) * fast_tanh(zB);
            } else {
                fg[ss] = fast_sigmoid(zA);
                og[ss] = fast_sigmoid(zB);
            }
        }
        bar_grp(barid);

        if (roleA) {
            // fc dot for state index t-1; the reference does NOT flip the
            // backward outputs: out position t' pairs hf(t') with hb(t').
            if (t > 0) {
                const float* hp = &sm.h[(t + 1) & 1][d][fss][fj * 8];
                float4 h0 = *(const float4*)hp;
                float4 h1 = *(const float4*)(hp + 4);
                float p = fw0.x * h0.x + fw0.y * h0.y + fw0.z * h0.z + fw0.w * h0.w
                        + fw1.x * h1.x + fw1.y * h1.y + fw1.z * h1.z + fw1.w * h1.w;
                p += __shfl_xor_sync(0xffffffffu, p, 1);
                p += __shfl_xor_sync(0xffffffffu, p, 2);
                p += __shfl_xor_sync(0xffffffffu, p, 4);
                if (fj == 0) {
                    if (d == 0) out[(b0 + fss) * T_LEN + (t - 1)] = p;  // fwd partial -> gmem
                    else        sm.pb[fss][t - 1] = p;                   // bwd partial, SAME position
                }
            }
        } else {
            // cell/hidden update; writes h(t) into buf[t&1]
            float* hw = &sm.h[t & 1][d][0][0];
            #pragma unroll
            for (int ss = 0; ss < SB; ++ss) {
                c[ss] = fmaf(fg[ss], c[ss], sm.abuf[d][k][ss]);
                hw[ss * HID + k] = og[ss] * fast_tanh(c[ss]);
            }
        }
        bar_grp(barid);
    }

    // final fc dot for state index T_LEN-1 (h in buf[(T_LEN-1)&1] = buf[1])
    if (roleA) {
        const float* hp = &sm.h[(T_LEN - 1) & 1][d][fss][fj * 8];
        float4 h0 = *(const float4*)hp;
        float4 h1 = *(const float4*)(hp + 4);
        float p = fw0.x * h0.x + fw0.y * h0.y + fw0.z * h0.z + fw0.w * h0.w
                + fw1.x * h1.x + fw1.y * h1.y + fw1.z * h1.z + fw1.w * h1.w;
        p += __shfl_xor_sync(0xffffffffu, p, 1);
        p += __shfl_xor_sync(0xffffffffu, p, 2);
        p += __shfl_xor_sync(0xffffffffu, p, 4);
        if (fj == 0) {
            if (d == 0) out[(b0 + fss) * T_LEN + (T_LEN - 1)] = p;
            else        sm.pb[fss][T_LEN - 1] = p;
        }
    }

    __syncthreads();   // fwd's gmem partials + bwd's smem partials all visible

    const float fcb = fc_b[0];
    for (int idx = tid; idx < SB * T_LEN; idx += NTH) {
        int ss = idx >> 10, tt = idx & (T_LEN - 1);
        float* po = out + (b0 + ss) * T_LEN + tt;
        *po = *po + sm.pb[ss][tt] + fcb;
    }
}

extern "C" void kernel_launch(void* const* d_in, const int* in_sizes, int n_in,
                              void* d_out, int out_size) {
    const float* x     = (const float*)d_in[0];
    const float* Wih_f = (const float*)d_in[1];
    const float* Whh_f = (const float*)d_in[2];
    const float* bih_f = (const float*)d_in[3];
    const float* bhh_f = (const float*)d_in[4];
    const float* Wih_b = (const float*)d_in[5];
    const float* Whh_b = (const float*)d_in[6];
    const float* bih_b = (const float*)d_in[7];
    const float* bhh_b = (const float*)d_in[8];
    const float* fc_w  = (const float*)d_in[9];
    const float* fc_b  = (const float*)d_in[10];
    float* out = (float*)d_out;

    const int B = in_sizes[0] / T_LEN;   // 1024
    const int grid = B / SB;             // 128 CTAs

    bilstm_kernel<<<grid, NTH>>>(x, Wih_f, Whh_f, bih_f, bhh_f,
                                 Wih_b, Whh_b, bih_b, bhh_b,
                                 fc_w, fc_b, out);
    (void)n_in; (void)out_size;
}

// round 8
// speedup vs baseline: 2.6325x; 2.6164x over previous
#include <cuda_runtime.h>
#include <cuda_fp16.h>
#include <cstdint>

#define T_LEN 1024
#define NTH   256
#define HSTR  136        // h-buffer row stride in halves (272 B -> conflict-free frags)

static __device__ __forceinline__ float fsig(float x) {
    return __fdividef(1.0f, 1.0f + __expf(-x));
}
static __device__ __forceinline__ float ftanh(float x) {
    return fmaf(-2.0f, __fdividef(1.0f, __expf(2.0f * x) + 1.0f), 1.0f);
}
static __device__ __forceinline__ uint32_t pack2(__half a, __half b) {
    __half2 t = __halves2half2(a, b);
    return *(uint32_t*)&t;
}
static __device__ __forceinline__ __half wsplit(float w, bool lo) {
    __half h = __float2half_rn(w);
    return lo ? __float2half_rn(w - __half2float(h)) : h;
}
static __device__ __forceinline__ void mma16816(float* d, const uint32_t* a, const uint32_t* b) {
    asm volatile(
        "mma.sync.aligned.m16n8k16.row.col.f32.f16.f16.f32 "
        "{%0,%1,%2,%3}, {%4,%5,%6,%7}, {%8,%9}, {%0,%1,%2,%3};"
        : "+f"(d[0]), "+f"(d[1]), "+f"(d[2]), "+f"(d[3])
        : "r"(a[0]), "r"(a[1]), "r"(a[2]), "r"(a[3]), "r"(b[0]), "r"(b[1]));
}

__global__ void out_init(float* out, const float* fc_b, int n) {
    int i = blockIdx.x * blockDim.x + threadIdx.x;
    if (i < n) out[i] = fc_b[0];
}

__global__ __launch_bounds__(NTH, 1)
void bilstm_mma(const float* __restrict__ x,
                const float* __restrict__ Wih_f, const float* __restrict__ Whh_f,
                const float* __restrict__ bih_f, const float* __restrict__ bhh_f,
                const float* __restrict__ Wih_b, const float* __restrict__ Whh_b,
                const float* __restrict__ bih_b, const float* __restrict__ bhh_b,
                const float* __restrict__ fc_w, float* __restrict__ out)
{
    __shared__ __align__(16) __half hs[2][16][HSTR];   // h hi (cols 0..63) / lo (64..127)
    __shared__ float psum[2][16][8];

    const int tid = threadIdx.x, wid = tid >> 5, lane = tid & 31;
    const int q = lane & 3, r = lane >> 2;
    const int dir = blockIdx.x & 1;
    const int b0 = (blockIdx.x >> 1) * 16;

    const float* Whh = dir ? Whh_b : Whh_f;
    const float* Wih = dir ? Wih_b : Wih_f;
    const float* bih = dir ? bih_b : bih_f;
    const float* bhh = dir ? bhh_b : bhh_f;

    // zero both h buffers
    for (int i = tid; i < 2 * 16 * HSTR; i += NTH) (&hs[0][0][0])[i] = __float2half(0.f);

    // ---- preload Whh^T B-fragments: bf[ks 0..7][nt 0..3][2 regs] ----
    // W column split: ks<4 -> hi of cols 16ks..; ks>=4 -> lo of cols 16(ks-4)..
    // W row for (nt, col nn): pair (2q',2q'+1) = (i,g) for even nt, (f,o) for odd nt
    uint32_t bf[8][4][2];
    {
        const int nn = r, qp = nn >> 1, odd = nn & 1;
        #pragma unroll
        for (int nt = 0; nt < 4; ++nt) {
            const int unit = 8 * wid + (nt >= 2 ? 4 : 0) + qp;
            const int row = ((nt & 1) ? (odd ? 192 : 64) : (odd ? 128 : 0)) + unit;
            const float* wr = Whh + row * 64;
            #pragma unroll
            for (int ks = 0; ks < 8; ++ks) {
                const bool lo = ks >= 4;
                const int wcol = (lo ? (ks - 4) : ks) * 16 + q * 2;
                bf[ks][nt][0] = pack2(wsplit(__ldg(wr + wcol),     lo),
                                      wsplit(__ldg(wr + wcol + 1), lo));
                bf[ks][nt][1] = pack2(wsplit(__ldg(wr + wcol + 8), lo),
                                      wsplit(__ldg(wr + wcol + 9), lo));
            }
        }
    }

    // gate-owner constants: units u1 = 8w+q, u2 = u1+4; streams r, r+8
    const int u1 = 8 * wid + q, u2 = u1 + 4;
    const float wi_i1 = Wih[u1], wi_f1 = Wih[64 + u1], wi_g1 = Wih[128 + u1], wi_o1 = Wih[192 + u1];
    const float wi_i2 = Wih[u2], wi_f2 = Wih[64 + u2], wi_g2 = Wih[128 + u2], wi_o2 = Wih[192 + u2];
    const float bi1 = bih[u1] + bhh[u1],             bf1 = bih[64 + u1] + bhh[64 + u1];
    const float bg1 = bih[128 + u1] + bhh[128 + u1], bo1 = bih[192 + u1] + bhh[192 + u1];
    const float bi2 = bih[u2] + bhh[u2],             bf2 = bih[64 + u2] + bhh[64 + u2];
    const float bg2 = bih[128 + u2] + bhh[128 + u2], bo2 = bih[192 + u2] + bhh[192 + u2];
    const float fcw1 = fc_w[dir * 64 + u1], fcw2 = fc_w[dir * 64 + u2];

    float cc[4] = {0.f, 0.f, 0.f, 0.f};   // cell states: (u1,r),(u1,r+8),(u2,r),(u2,r+8)
    __syncthreads();

    const int amap[12] = {0,1,2,3, 0,1,2,3, 4,5,6,7};
    const int bmap[12] = {0,1,2,3, 4,5,6,7, 0,1,2,3};

    for (int t = 0; t < T_LEN; ++t) {
        // flush previous step's fc partials
        if (t > 0 && wid == 0 && lane < 16) {
            const float* ps = &psum[(t - 1) & 1][lane][0];
            float s = 0.f;
            #pragma unroll
            for (int j = 0; j < 8; ++j) s += ps[j];
            atomicAdd(out + (size_t)(b0 + lane) * T_LEN + (t - 1), s);
        }

        // ---- load A (h) fragments from buffer holding h(t-1) ----
        const __half* hb = &hs[(t & 1) ^ 1][0][0];
        uint32_t af[8][4];
        #pragma unroll
        for (int jj = 0; jj < 8; ++jj) {
            const int c0 = jj * 16 + q * 2;
            af[jj][0] = *(const uint32_t*)(hb + r * HSTR + c0);
            af[jj][1] = *(const uint32_t*)(hb + (r + 8) * HSTR + c0);
            af[jj][2] = *(const uint32_t*)(hb + r * HSTR + c0 + 8);
            af[jj][3] = *(const uint32_t*)(hb + (r + 8) * HSTR + c0 + 8);
        }

        // ---- 48 HMMA: Z[16 streams, 32 gate-rows of this warp] ----
        float d[4][4] = {{0.f,0.f,0.f,0.f},{0.f,0.f,0.f,0.f},{0.f,0.f,0.f,0.f},{0.f,0.f,0.f,0.f}};
        #pragma unroll
        for (int nt = 0; nt < 4; ++nt)
            #pragma unroll
            for (int ks = 0; ks < 12; ++ks)
                mma16816(d[nt], af[amap[ks]], bf[bmap[ks]][nt]);

        // ---- gates: fully thread-local ----
        const int xt = dir ? (T_LEN - 1 - t) : t;
        const float xv0 = __ldg(x + (size_t)(b0 + r) * T_LEN + xt);
        const float xv1 = __ldg(x + (size_t)(b0 + r + 8) * T_LEN + xt);

        float hval[4];
        #pragma unroll
        for (int cidx = 0; cidx < 4; ++cidx) {
            const int ti = (cidx >= 2) ? 2 : 0;          // nt pair (0,1) for u1, (2,3) for u2
            const int co = (cidx & 1) ? 2 : 0;           // d-reg offset: stream r vs r+8
            const float xv = (cidx & 1) ? xv1 : xv0;
            const bool isU2 = cidx >= 2;
            const float zi = d[ti][co]     + fmaf(xv, isU2 ? wi_i2 : wi_i1, isU2 ? bi2 : bi1);
            const float zg = d[ti][co + 1] + fmaf(xv, isU2 ? wi_g2 : wi_g1, isU2 ? bg2 : bg1);
            const float zf = d[ti + 1][co]     + fmaf(xv, isU2 ? wi_f2 : wi_f1, isU2 ? bf2 : bf1);
            const float zo = d[ti + 1][co + 1] + fmaf(xv, isU2 ? wi_o2 : wi_o1, isU2 ? bo2 : bo1);
            cc[cidx] = fmaf(fsig(zf), cc[cidx], fsig(zi) * ftanh(zg));
            hval[cidx] = fsig(zo) * ftanh(cc[cidx]);
        }

        // ---- store h(t) hi/lo into buffer t&1 ----
        __half* hw = &hs[t & 1][0][0];
        #pragma unroll
        for (int cidx = 0; cidx < 4; ++cidx) {
            const int ss = (cidx & 1) ? (r + 8) : r;
            const int uu = (cidx >= 2) ? u2 : u1;
            const __half hh = __float2half_rn(hval[cidx]);
            const __half hl = __float2half_rn(hval[cidx] - __half2float(hh));
            hw[ss * HSTR + uu] = hh;
            hw[ss * HSTR + 64 + uu] = hl;
        }

        // ---- fc partials (exact fp32 h) ----
        float pr  = fcw1 * hval[0] + fcw2 * hval[2];
        float pr8 = fcw1 * hval[1] + fcw2 * hval[3];
        pr  += __shfl_xor_sync(0xffffffffu, pr, 1);
        pr  += __shfl_xor_sync(0xffffffffu, pr, 2);
        pr8 += __shfl_xor_sync(0xffffffffu, pr8, 1);
        pr8 += __shfl_xor_sync(0xffffffffu, pr8, 2);
        if (q == 0) {
            psum[t & 1][r][wid] = pr;
            psum[t & 1][r + 8][wid] = pr8;
        }
        __syncthreads();
    }

    // final flush (t = T_LEN-1)
    if (wid == 0 && lane < 16) {
        const float* ps = &psum[(T_LEN - 1) & 1][lane][0];
        float s = 0.f;
        #pragma unroll
        for (int j = 0; j < 8; ++j) s += ps[j];
        atomicAdd(out + (size_t)(b0 + lane) * T_LEN + (T_LEN - 1), s);
    }
}

extern "C" void kernel_launch(void* const* d_in, const int* in_sizes, int n_in,
                              void* d_out, int out_size) {
    const float* x     = (const float*)d_in[0];
    const float* Wih_f = (const float*)d_in[1];
    const float* Whh_f = (const float*)d_in[2];
    const float* bih_f = (const float*)d_in[3];
    const float* bhh_f = (const float*)d_in[4];
    const float* Wih_b = (const float*)d_in[5];
    const float* Whh_b = (const float*)d_in[6];
    const float* bih_b = (const float*)d_in[7];
    const float* bhh_b = (const float*)d_in[8];
    const float* fc_w  = (const float*)d_in[9];
    const float* fc_b  = (const float*)d_in[10];
    float* out = (float*)d_out;

    out_init<<<(out_size + 255) / 256, 256>>>(out, fc_b, out_size);

    const int B = in_sizes[0] / T_LEN;   // 1024
    const int grid = (B / 16) * 2;       // 128 CTAs: (batch-group, direction)
    bilstm_mma<<<grid, NTH>>>(x, Wih_f, Whh_f, bih_f, bhh_f,
                              Wih_b, Whh_b, bih_b, bhh_b, fc_w, out);
    (void)n_in;
}